// round 1
// baseline (speedup 1.0000x reference)
#include <cuda_runtime.h>
#include <math.h>

#define BB 256
#define HH 512
#define CC 512
#define NL 128
#define TT 23      // decode steps (L-1)
#define LSEQ 24
#define VV 64
#define BH (BB*HH)

// ---------------- static scratch (allowed: __device__ globals) ----------------
__device__ float g_Ws[(size_t)BB*NL*HH];   // 64 MB: precomputed states @ attn_W^T + b
__device__ float g_xs[(size_t)TT*BH];      // [t][b][h] embedded inputs
__device__ float g_ys[(size_t)TT*BH];      // [t][b][h] decoder outputs
__device__ float g_y0[BH];
__device__ float g_h0buf[2][BH];
__device__ float g_h1buf[2][BH];
__device__ float g_Uh[BH];
__device__ float g_ctx[BH];
__device__ float g_nll[TT*BB];
__device__ float g_msk[TT*BB];

__device__ __forceinline__ float sigmoidf_(float x){ return 1.f/(1.f+expf(-x)); }

// ---------------- init hidden states ----------------
__global__ void k_inith(const float* __restrict__ init_state,
                        float* __restrict__ h0, float* __restrict__ h1){
  int idx = blockIdx.x*blockDim.x + threadIdx.x;
  if (idx < BH){
    int j = idx & (HH-1);
    h0[idx] = init_state[j];        // layer 0
    h1[idx] = init_state[HH + j];   // layer 1
  }
}

// ---------------- embedding gather: xs[t][b][h] ----------------
__global__ void k_embed(const float* __restrict__ emb, const int* __restrict__ seq,
                        float* __restrict__ xs){
  int idx = blockIdx.x*blockDim.x + threadIdx.x;
  if (idx < TT*BH){
    int h = idx & (HH-1);
    int r = idx >> 9;          // t*256 + b
    int b = r & (BB-1);
    int t = r >> 8;
    int tok = seq[b*LSEQ + t];
    xs[idx] = emb[(size_t)tok*HH + h];
  }
}

// ---------------- Ws GEMM: Ws[b*128+l, h] = sum_c enc[b,c,l]*Ww[h,c] + Wb[h] ----------------
// M = 32768, N = 512, K = 512. 64x64 tiles, 4x4 per thread, 256 threads.
__global__ void __launch_bounds__(256) k_ws(const float* __restrict__ enc,
                                            const float* __restrict__ Ww,
                                            const float* __restrict__ Wb,
                                            float* __restrict__ Ws){
  __shared__ float At[16][68];
  __shared__ float Wt[16][68];
  int m0 = blockIdx.x*64;
  int n0 = blockIdx.y*64;
  int b  = m0 >> 7;            // 64-tile always within one b (128 l's)
  int l0 = m0 & 127;
  int tid = threadIdx.x;
  int tm = tid & 15, tn = tid >> 4;
  float acc[4][4] = {};
  for (int kc = 0; kc < 512; kc += 16){
    #pragma unroll
    for (int i = 0; i < 4; i++){
      int e = tid + i*256;
      int kk = e >> 6, mm = e & 63;
      At[kk][mm] = enc[(size_t)b*(CC*NL) + (size_t)(kc+kk)*NL + l0 + mm];
    }
    #pragma unroll
    for (int i = 0; i < 4; i++){
      int e = tid + i*256;
      int nn = e >> 4, kk = e & 15;
      Wt[kk][nn] = Ww[(size_t)(n0+nn)*CC + kc + kk];
    }
    __syncthreads();
    #pragma unroll
    for (int kk = 0; kk < 16; kk++){
      float4 a = *(const float4*)&At[kk][tm*4];
      float4 w = *(const float4*)&Wt[kk][tn*4];
      acc[0][0]+=a.x*w.x; acc[0][1]+=a.x*w.y; acc[0][2]+=a.x*w.z; acc[0][3]+=a.x*w.w;
      acc[1][0]+=a.y*w.x; acc[1][1]+=a.y*w.y; acc[1][2]+=a.y*w.z; acc[1][3]+=a.y*w.w;
      acc[2][0]+=a.z*w.x; acc[2][1]+=a.z*w.y; acc[2][2]+=a.z*w.z; acc[2][3]+=a.z*w.w;
      acc[3][0]+=a.w*w.x; acc[3][1]+=a.w*w.y; acc[3][2]+=a.w*w.z; acc[3][3]+=a.w*w.w;
    }
    __syncthreads();
  }
  #pragma unroll
  for (int mi = 0; mi < 4; mi++){
    int m = m0 + tm*4 + mi;
    #pragma unroll
    for (int ni = 0; ni < 4; ni++){
      int n = n0 + tn*4 + ni;
      Ws[(size_t)m*HH + n] = acc[mi][ni] + Wb[n];
    }
  }
}

// ---------------- generic small GEMM: C = concat(A1,A2) @ W^T + bias (opt relu) ----------------
// 32(m) x 64(n) tiles, 2x4 per thread, 256 threads. K multiple of 16.
__global__ void __launch_bounds__(256) k_gemm(const float* __restrict__ A1, int wA1,
                                              const float* __restrict__ A2, int wA2,
                                              const float* __restrict__ W,
                                              const float* __restrict__ bias,
                                              float* __restrict__ Cout,
                                              int N, int K, int relu){
  __shared__ float At[16][34];
  __shared__ float Wt[16][68];
  int m0 = blockIdx.x*32, n0 = blockIdx.y*64;
  int tid = threadIdx.x;
  int tm = tid & 15, tn = tid >> 4;
  float acc[2][4] = {};
  for (int kc = 0; kc < K; kc += 16){
    {
      int bb = tid >> 3;
      int kk = (tid & 7)*2;
      #pragma unroll
      for (int u = 0; u < 2; u++){
        int col = kc + kk + u;
        float v = (col < wA1) ? A1[(size_t)(m0+bb)*wA1 + col]
                              : A2[(size_t)(m0+bb)*wA2 + (col - wA1)];
        At[kk+u][bb] = v;
      }
    }
    #pragma unroll
    for (int i = 0; i < 4; i++){
      int e = tid + i*256;
      int r = e >> 4, kk = e & 15;
      Wt[kk][r] = W[(size_t)(n0+r)*K + kc + kk];
    }
    __syncthreads();
    #pragma unroll
    for (int kk = 0; kk < 16; kk++){
      float2 a = *(const float2*)&At[kk][tm*2];
      float4 w = *(const float4*)&Wt[kk][tn*4];
      acc[0][0]+=a.x*w.x; acc[0][1]+=a.x*w.y; acc[0][2]+=a.x*w.z; acc[0][3]+=a.x*w.w;
      acc[1][0]+=a.y*w.x; acc[1][1]+=a.y*w.y; acc[1][2]+=a.y*w.z; acc[1][3]+=a.y*w.w;
    }
    __syncthreads();
  }
  #pragma unroll
  for (int mi = 0; mi < 2; mi++){
    int m = m0 + tm*2 + mi;
    #pragma unroll
    for (int ni = 0; ni < 4; ni++){
      int n = n0 + tn*4 + ni;
      float v = acc[mi][ni] + bias[n];
      if (relu) v = fmaxf(v, 0.f);
      Cout[(size_t)m*N + n] = v;
    }
  }
}

// ---------------- fused GRU cell: both gate GEMMs + pointwise ----------------
// input = concat(srcA[wA], srcB[wB]) (K1 = wA+wB), hprev width 512.
// 32(b) x 32(j) tile, 2x2 per thread x 4 gate-accumulator sets (r,z,n_i,n_h).
#define GRU_MAC(AR, AZ, AN)                                              \
  {                                                                      \
    float2 a  = *(const float2*)&At[kk][tb*2];                           \
    float2 wr = *(const float2*)&Wt[0][kk][tj*2];                        \
    float2 wz = *(const float2*)&Wt[1][kk][tj*2];                        \
    float2 wn = *(const float2*)&Wt[2][kk][tj*2];                        \
    AR[0][0]+=a.x*wr.x; AR[0][1]+=a.x*wr.y; AR[1][0]+=a.y*wr.x; AR[1][1]+=a.y*wr.y; \
    AZ[0][0]+=a.x*wz.x; AZ[0][1]+=a.x*wz.y; AZ[1][0]+=a.y*wz.x; AZ[1][1]+=a.y*wz.y; \
    AN[0][0]+=a.x*wn.x; AN[0][1]+=a.x*wn.y; AN[1][0]+=a.y*wn.x; AN[1][1]+=a.y*wn.y; \
  }

__global__ void __launch_bounds__(256) k_gru(const float* __restrict__ srcA, int wA,
                                             const float* __restrict__ srcB, int wB,
                                             const float* __restrict__ hprev,
                                             const float* __restrict__ wih,
                                             const float* __restrict__ whh,
                                             const float* __restrict__ bih,
                                             const float* __restrict__ bhh,
                                             float* __restrict__ hnew){
  __shared__ float At[16][34];
  __shared__ float Wt[3][16][34];
  int b0 = blockIdx.x*32, j0 = blockIdx.y*32;
  int tid = threadIdx.x;
  int tb = tid & 15, tj = tid >> 4;
  float accr[2][2]={}, accz[2][2]={}, accni[2][2]={}, accnh[2][2]={};
  const int K1 = wA + wB;

  // phase 0: input @ wih^T  (gates r,z -> accr/accz, n -> accni)
  for (int kc = 0; kc < K1; kc += 16){
    {
      int bb = tid >> 3;
      int kk = (tid & 7)*2;
      #pragma unroll
      for (int u = 0; u < 2; u++){
        int col = kc + kk + u;
        float v = (col < wA) ? srcA[(size_t)(b0+bb)*wA + col]
                             : srcB[(size_t)(b0+bb)*wB + (col - wA)];
        At[kk+u][bb] = v;
      }
    }
    #pragma unroll
    for (int i = 0; i < 6; i++){
      int e = tid + i*256;
      int r = e >> 4, kk = e & 15;
      int g = r >> 5, jj = r & 31;
      Wt[g][kk][jj] = wih[(size_t)((g<<9) + j0 + jj)*K1 + kc + kk];
    }
    __syncthreads();
    #pragma unroll
    for (int kk = 0; kk < 16; kk++) GRU_MAC(accr, accz, accni);
    __syncthreads();
  }

  // phase 1: hprev @ whh^T  (gates r,z -> accr/accz, n -> accnh)
  for (int kc = 0; kc < HH; kc += 16){
    {
      int bb = tid >> 3;
      int kk = (tid & 7)*2;
      #pragma unroll
      for (int u = 0; u < 2; u++){
        int col = kc + kk + u;
        At[kk+u][bb] = hprev[(size_t)(b0+bb)*HH + col];
      }
    }
    #pragma unroll
    for (int i = 0; i < 6; i++){
      int e = tid + i*256;
      int r = e >> 4, kk = e & 15;
      int g = r >> 5, jj = r & 31;
      Wt[g][kk][jj] = whh[(size_t)((g<<9) + j0 + jj)*HH + kc + kk];
    }
    __syncthreads();
    #pragma unroll
    for (int kk = 0; kk < 16; kk++) GRU_MAC(accr, accz, accnh);
    __syncthreads();
  }

  // epilogue
  #pragma unroll
  for (int bi = 0; bi < 2; bi++){
    int b = b0 + tb*2 + bi;
    #pragma unroll
    for (int ji = 0; ji < 2; ji++){
      int j = j0 + tj*2 + ji;
      float r  = sigmoidf_(accr[bi][ji] + bih[j]      + bhh[j]);
      float z  = sigmoidf_(accz[bi][ji] + bih[HH+j]   + bhh[HH+j]);
      float hn = accnh[bi][ji] + bhh[2*HH+j];
      float n  = tanhf(accni[bi][ji] + bih[2*HH+j] + r*hn);
      float hp = hprev[(size_t)b*HH + j];
      hnew[(size_t)b*HH + j] = (1.f - z)*n + z*hp;
    }
  }
}

// ---------------- attention: scores, softmax, context. one block per batch ----------------
__global__ void __launch_bounds__(256) k_attn(const float* __restrict__ Ws,
                                              const float* __restrict__ Uh,
                                              const float* __restrict__ enc,
                                              const float* __restrict__ vw,
                                              const float* __restrict__ vb,
                                              float* __restrict__ ctx){
  __shared__ float uv[HH];
  __shared__ float vs[HH];
  __shared__ float sc[NL];
  int b = blockIdx.x;
  int tid = threadIdx.x;
  int warp = tid >> 5, lane = tid & 31;
  for (int i = tid; i < HH; i += 256){
    uv[i] = Uh[(size_t)b*HH + i];
    vs[i] = vw[i];
  }
  __syncthreads();
  float vbias = vb[0];
  // scores[l] = sum_h relu(Ws[b,l,h] + Uh[b,h]) * v[h] + vb
  for (int l = warp; l < NL; l += 8){
    const float* wr = Ws + ((size_t)b*NL + l)*HH;
    float s = 0.f;
    #pragma unroll 4
    for (int h = lane; h < HH; h += 32){
      float e = wr[h] + uv[h];
      e = fmaxf(e, 0.f);
      s += e * vs[h];
    }
    #pragma unroll
    for (int o = 16; o; o >>= 1) s += __shfl_xor_sync(0xffffffffu, s, o);
    if (lane == 0) sc[l] = s + vbias;
  }
  __syncthreads();
  // softmax over 128 (warp 0)
  if (tid < 32){
    float m = -1e30f;
    for (int l = tid; l < NL; l += 32) m = fmaxf(m, sc[l]);
    #pragma unroll
    for (int o = 16; o; o >>= 1) m = fmaxf(m, __shfl_xor_sync(0xffffffffu, m, o));
    float s = 0.f;
    for (int l = tid; l < NL; l += 32){ float e = expf(sc[l]-m); sc[l] = e; s += e; }
    #pragma unroll
    for (int o = 16; o; o >>= 1) s += __shfl_xor_sync(0xffffffffu, s, o);
    float inv = 1.f/s;
    for (int l = tid; l < NL; l += 32) sc[l] *= inv;
  }
  __syncthreads();
  // ctx[c] = sum_l a[l] * enc[b,c,l]
  for (int c = warp; c < CC; c += 8){
    const float* er = enc + ((size_t)b*CC + c)*NL;
    float s = 0.f;
    #pragma unroll
    for (int l = lane; l < NL; l += 32) s += er[l] * sc[l];
    #pragma unroll
    for (int o = 16; o; o >>= 1) s += __shfl_xor_sync(0xffffffffu, s, o);
    if (lane == 0) ctx[(size_t)b*CC + c] = s;
  }
}

// ---------------- logits + per-token masked NLL ----------------
__global__ void __launch_bounds__(128) k_logits(const float* __restrict__ ys,
                                                const float* __restrict__ clsw,
                                                const float* __restrict__ clsb,
                                                const int* __restrict__ seq,
                                                float* __restrict__ nll,
                                                float* __restrict__ msk){
  __shared__ float yb[HH];
  __shared__ float lg[VV];
  int t = blockIdx.x >> 8;
  int b = blockIdx.x & 255;
  int tid = threadIdx.x;
  for (int i = tid; i < HH; i += 128)
    yb[i] = ys[((size_t)t*BB + b)*HH + i];
  __syncthreads();
  {
    int v = tid >> 1, half = tid & 1;
    const float4* wr = (const float4*)(clsw + (size_t)v*HH + half*256);
    const float4* yr = (const float4*)(yb + half*256);
    float s = 0.f;
    #pragma unroll 8
    for (int i = 0; i < 64; i++){
      float4 w = wr[i], y = yr[i];
      s += w.x*y.x + w.y*y.y + w.z*y.z + w.w*y.w;
    }
    s += __shfl_xor_sync(0xffffffffu, s, 1);
    if (!half) lg[v] = s + clsb[v];
  }
  __syncthreads();
  if (tid == 0){
    float m = lg[0];
    #pragma unroll
    for (int v = 1; v < VV; v++) m = fmaxf(m, lg[v]);
    float se = 0.f;
    #pragma unroll
    for (int v = 0; v < VV; v++) se += expf(lg[v]-m);
    int label = seq[b*LSEQ + t + 1];
    float lp = lg[label] - m - logf(se);
    bool mk = label > 0;
    nll[blockIdx.x] = mk ? -lp : 0.f;
    msk[blockIdx.x] = mk ? 1.f : 0.f;
  }
}

// ---------------- deterministic final reduction ----------------
__global__ void __launch_bounds__(256) k_reduce(const float* __restrict__ nll,
                                                const float* __restrict__ msk,
                                                float* __restrict__ out){
  __shared__ float sn[256], sm[256];
  int tid = threadIdx.x;
  float a = 0.f, c = 0.f;
  for (int i = tid; i < TT*BB; i += 256){ a += nll[i]; c += msk[i]; }
  sn[tid] = a; sm[tid] = c;
  __syncthreads();
  for (int o = 128; o; o >>= 1){
    if (tid < o){ sn[tid] += sn[tid+o]; sm[tid] += sm[tid+o]; }
    __syncthreads();
  }
  if (tid == 0) out[0] = sn[0] / sm[0];
}

// ---------------- host orchestration (host code runs at capture time only) ----------------
extern "C" void kernel_launch(void* const* d_in, const int* in_sizes, int n_in,
                              void* d_out, int out_size){
  (void)in_sizes; (void)n_in; (void)out_size;
  const float* enc   = (const float*)d_in[0];
  const int*   seq   = (const int*)  d_in[1];
  const float* emb   = (const float*)d_in[3];
  const float* inis  = (const float*)d_in[4];
  const float* aWw   = (const float*)d_in[5];
  const float* aWb   = (const float*)d_in[6];
  const float* aUw   = (const float*)d_in[7];
  const float* aUb   = (const float*)d_in[8];
  const float* avw   = (const float*)d_in[9];
  const float* avb   = (const float*)d_in[10];
  const float* fcw   = (const float*)d_in[11];
  const float* fcb   = (const float*)d_in[12];
  const float* clsw  = (const float*)d_in[13];
  const float* clsb  = (const float*)d_in[14];
  const float* g0wih = (const float*)d_in[15];
  const float* g0whh = (const float*)d_in[16];
  const float* g0bih = (const float*)d_in[17];
  const float* g0bhh = (const float*)d_in[18];
  const float* g1wih = (const float*)d_in[19];
  const float* g1whh = (const float*)d_in[20];
  const float* g1bih = (const float*)d_in[21];
  const float* g1bhh = (const float*)d_in[22];

  float *Ws, *xs, *ys, *y0, *h0b, *h1b, *Uh, *ctx, *nll, *msk;
  cudaGetSymbolAddress((void**)&Ws,  g_Ws);
  cudaGetSymbolAddress((void**)&xs,  g_xs);
  cudaGetSymbolAddress((void**)&ys,  g_ys);
  cudaGetSymbolAddress((void**)&y0,  g_y0);
  cudaGetSymbolAddress((void**)&h0b, g_h0buf);
  cudaGetSymbolAddress((void**)&h1b, g_h1buf);
  cudaGetSymbolAddress((void**)&Uh,  g_Uh);
  cudaGetSymbolAddress((void**)&ctx, g_ctx);
  cudaGetSymbolAddress((void**)&nll, g_nll);
  cudaGetSymbolAddress((void**)&msk, g_msk);

  // precompute
  k_inith<<<(BH+255)/256, 256>>>(inis, h0b, h1b);
  k_embed<<<(TT*BH+255)/256, 256>>>(emb, seq, xs);
  k_ws<<<dim3(512, 8), 256>>>(enc, aWw, aWb, Ws);

  // y0 = out_proj(attn(h1_init), h1_init)
  k_gemm<<<dim3(8,8), 256>>>(h1b, HH, (const float*)nullptr, 0, aUw, aUb, Uh, HH, HH, 0);
  k_attn<<<BB, 256>>>(Ws, Uh, enc, avw, avb, ctx);
  k_gemm<<<dim3(8,8), 256>>>(ctx, CC, h1b, HH, fcw, fcb, y0, HH, CC+HH, 1);

  const float* yprev = y0;
  for (int t = 0; t < TT; t++){
    float* h0r = h0b + (size_t)(t & 1)*BH;
    float* h0w = h0b + (size_t)((t+1) & 1)*BH;
    float* h1r = h1b + (size_t)(t & 1)*BH;
    float* h1w = h1b + (size_t)((t+1) & 1)*BH;
    // GRU layer 0: input [y_prev, x_t]
    k_gru<<<dim3(8,16), 256>>>(yprev, HH, xs + (size_t)t*BH, HH,
                               h0r, g0wih, g0whh, g0bih, g0bhh, h0w);
    // GRU layer 1: input h_l0
    k_gru<<<dim3(8,16), 256>>>(h0w, HH, (const float*)nullptr, 0,
                               h1r, g1wih, g1whh, g1bih, g1bhh, h1w);
    // attention on h_l1
    k_gemm<<<dim3(8,8), 256>>>(h1w, HH, (const float*)nullptr, 0, aUw, aUb, Uh, HH, HH, 0);
    k_attn<<<BB, 256>>>(Ws, Uh, enc, avw, avb, ctx);
    // out_proj -> ys[t]
    k_gemm<<<dim3(8,8), 256>>>(ctx, CC, h1w, HH, fcw, fcb,
                               ys + (size_t)t*BH, HH, CC+HH, 1);
    yprev = ys + (size_t)t*BH;
  }

  k_logits<<<TT*BB, 128>>>(ys, clsw, clsb, seq, nll, msk);
  k_reduce<<<1, 256>>>(nll, msk, (float*)d_out);
}